// round 12
// baseline (speedup 1.0000x reference)
#include <cuda_runtime.h>
#include <cuda_fp16.h>
#include <cstdint>

#define NB 8
#define NN 64
#define NT 50
#define TO 49
#define ND 4
#define NH 64
#define EPN 63
#define NNODES (NB * TO * NN)     // 25088
#define NTILES (NNODES / 2)       // 12544
#define GRID 296
#define EREL (NN * EPN)           // 4032
#define NBT (NB * TO)             // 392

typedef unsigned int u32;

__device__ __half g_uh[NNODES * NH];      // fp16 u' = W1r@x + b1
__device__ __half g_vh[NNODES * NH];      // fp16 v  = W1s@x
__device__ float g_agg[NNODES * NH];      // edge-aggregated messages
__device__ float g_w1t[(ND + NH) * NH];   // out1_w^T: [k][o]
__device__ float g_w2nt[NH * NH];         // out2_w^T: [k][o]

// ---- edge-kernel smem layout (bytes) ---------------------------------------
#define OFF_A    0                // 128 rows x 128B fp16 = 16384 (SW128)
#define OFF_RT   16384            // 128 f = 512
#define OFF_PART 16896            // 8 x 64 f = 2048
#define OFF_BIAS 18944            // 64 f = 256
#define SMEM_SZ  19200

#define SWZ(o) ((o) ^ (((o) >> 3) & 0x70))

static __device__ __forceinline__ u32 smem_u32(const void* p) {
    u32 a;
    asm("{ .reg .u64 t; cvta.to.shared.u64 t, %1; cvt.u32.u64 %0, t; }" : "=r"(a) : "l"(p));
    return a;
}
static __device__ __forceinline__ void ldm4(u32* r, u32 addr) {
    asm volatile("ldmatrix.sync.aligned.m8n8.x4.shared.b16 {%0,%1,%2,%3}, [%4];"
        : "=r"(r[0]), "=r"(r[1]), "=r"(r[2]), "=r"(r[3]) : "r"(addr));
}
static __device__ __forceinline__ void mma_f16(float* c, const u32* a, u32 b0, u32 b1) {
    asm volatile("mma.sync.aligned.m16n8k16.row.col.f32.f16.f16.f32 "
        "{%0,%1,%2,%3}, {%4,%5,%6,%7}, {%8,%9}, {%0,%1,%2,%3};"
        : "+f"(c[0]), "+f"(c[1]), "+f"(c[2]), "+f"(c[3])
        : "r"(a[0]), "r"(a[1]), "r"(a[2]), "r"(a[3]), "r"(b0), "r"(b1));
}
static __device__ __forceinline__ u32 hfx2(float x, float y) {
    __half2 p = __floats2half2_rn(x, y);
    return *(u32*)&p;
}
static __device__ __forceinline__ u32 hadd2_relu(u32 a, u32 b) {
    __half2 s = __hadd2(*(__half2*)&a, *(__half2*)&b);
    __half2 z = __float2half2_rn(0.f);
    __half2 r = __hmax2(s, z);
    return *(u32*)&r;
}

// ---------------------------------------------------------------------------
// Kernel 1: per-node fc1 factorization (fp32 math, fp16 store) + transposes.
__global__ void k_node_embed(const float* __restrict__ inputs,
                             const float* __restrict__ fc1_w,
                             const float* __restrict__ fc1_b,
                             const float* __restrict__ out1_w,
                             const float* __restrict__ out2_w) {
    int gid = blockIdx.x * blockDim.x + threadIdx.x;
    if (gid < (ND + NH) * NH) {
        int k = gid >> 6, o = gid & 63;
        g_w1t[k * NH + o] = out1_w[o * (ND + NH) + k];
    }
    if (gid < NH * NH) {
        int k = gid >> 6, o = gid & 63;
        g_w2nt[k * NH + o] = out2_w[o * NH + k];
    }
    if (gid >= NNODES * NH) return;
    int h    = gid & 63;
    int node = gid >> 6;
    int n    = node & 63;
    int bt   = node >> 6;
    int t    = bt % TO;
    int b    = bt / TO;

    const float* x = inputs + (((size_t)b * NN + n) * NT + t) * ND;
    const float* w = fc1_w + NH * 2 * ND + h * 2 * ND;
    float u = fc1_b[NH + h];
    float v = 0.f;
#pragma unroll
    for (int d = 0; d < ND; d++) {
        u += w[d] * x[d];
        v += w[ND + d] * x[d];
    }
    g_uh[gid] = __float2half_rn(u);
    g_vh[gid] = __float2half_rn(v);
}

// ---------------------------------------------------------------------------
// Kernel 2: persistent mma.sync edge-GEMM, fp16 single-pass.
// 2 nodes/iteration. Warp = (node mh = wid>>2, row-quarter mq = wid&3):
// owns 16 rows x ALL 64 cols; full W2 fp16 B-fragments in 64 regs; A
// fragments loaded ONCE per warp (LDSM /4). Row-reduction in-register +
// shfl; cross-quarter reduce via small smem partial.
__global__ void __launch_bounds__(256, 2)
k_edge_mma(const float* __restrict__ rel_type,
           const float* __restrict__ fc2_w, const float* __restrict__ fc2_b) {
    __shared__ __align__(1024) char smem[SMEM_SZ];
    const u32 smb = smem_u32(smem);
    const int tid  = threadIdx.x;
    const int lane = tid & 31;
    const int wid  = tid >> 5;
    const int mh   = wid >> 2;       // node within tile (0/1)
    const int mq   = wid & 3;        // row quarter (16 rows)

    float* rt_s   = (float*)(smem + OFF_RT);    // [2][64]
    float* part_s = (float*)(smem + OFF_PART);  // [8][64]
    float* bias_s = (float*)(smem + OFF_BIAS);  // [64]

    if (tid < 64) bias_s[tid] = fc2_b[NH + tid];

    // --- full W2 as fp16 B-fragments in registers, once.
    // nt = 8-col group; col = nt*8 + (lane>>2); k0 = kt*16 + (lane&3)*2.
    u32 bfr[4][8][2];
#pragma unroll
    for (int kt = 0; kt < 4; kt++)
#pragma unroll
        for (int nt = 0; nt < 8; nt++) {
            int k0  = kt * 16 + (lane & 3) * 2;
            int col = nt * 8 + (lane >> 2);
            const float* wc = fc2_w + NH * NH + col * NH;
            bfr[kt][nt][0] = hfx2(wc[k0],     wc[k0 + 1]);
            bfr[kt][nt][1] = hfx2(wc[k0 + 8], wc[k0 + 9]);
        }

    for (int tile = blockIdx.x; tile < NTILES; tile += GRID) {
        const int node0 = tile * 2;
        const int bt = node0 >> 6;
        const int b  = bt / TO;
        const int n0 = node0 & 63;

        __syncthreads();   // prev iteration's rt/A/part consumers retired

        if (tid < 128) {
            int nl = tid >> 6, s = tid & 63;
            rt_s[tid] = (s < EPN)
                ? rel_type[((size_t)b * EREL + (n0 + nl) * EPN + s) * 2 + 1] : 0.f;
        }

        // --- stage A, coalesced: warp covers 2 full 128B rows per iteration.
        {
            const int seg = lane & 15;            // 8B chunk
            const int rl  = lane >> 4;
#pragma unroll
            for (int it = 0; it < 8; it++) {
                const int r  = wid * 16 + it * 2 + rl;
                const int nl = r >> 6;
                const int s  = r & 63;
                const int nr = n0 + nl;
                const int send = (s >= EPN) ? nr : (s + (s >= nr ? 1 : 0));
                const uint2* uu = (const uint2*)(g_uh + ((size_t)(node0 + nl)) * NH) + seg;
                const uint2* vv = (const uint2*)(g_vh + ((size_t)(bt * NN) + send) * NH) + seg;
                uint2 ua = *uu;
                uint2 va = *vv;
                uint2 hv;
                hv.x = hadd2_relu(ua.x, va.x);
                hv.y = hadd2_relu(ua.y, va.y);
                u32 off = r * 128 + seg * 8;
                *(uint2*)(smem + OFF_A + SWZ(off)) = hv;
            }
        }
        __syncthreads();

        // --- MMA: single pass, 4 kt x 8 nt, A loaded once per kt.
        float acc[8][4];
#pragma unroll
        for (int nt = 0; nt < 8; nt++)
#pragma unroll
            for (int q = 0; q < 4; q++) acc[nt][q] = 0.f;

#pragma unroll
        for (int kt = 0; kt < 4; kt++) {
            u32 a[4];
            u32 o = (mh * 64 + mq * 16 + (lane & 15)) * 128
                  + kt * 32 + (lane >> 4) * 16;
            ldm4(a, smb + OFF_A + SWZ(o));
#pragma unroll
            for (int nt = 0; nt < 8; nt++)
                mma_f16(acc[nt], a, bfr[kt][nt][0], bfr[kt][nt][1]);
        }

        // --- epilogue: relu(+bias)*rt, reduce over this warp's 16 rows.
        const float r0 = rt_s[mh * 64 + mq * 16 + (lane >> 2)];
        const float r8 = rt_s[mh * 64 + mq * 16 + (lane >> 2) + 8];
        float s[16];
#pragma unroll
        for (int nt = 0; nt < 8; nt++) {
            float b0 = bias_s[nt * 8 + (lane & 3) * 2];
            float b1 = bias_s[nt * 8 + (lane & 3) * 2 + 1];
            s[nt * 2]     = fmaxf(acc[nt][0] + b0, 0.f) * r0
                          + fmaxf(acc[nt][2] + b0, 0.f) * r8;
            s[nt * 2 + 1] = fmaxf(acc[nt][1] + b1, 0.f) * r0
                          + fmaxf(acc[nt][3] + b1, 0.f) * r8;
        }
#pragma unroll
        for (int off = 4; off < 32; off <<= 1)
#pragma unroll
            for (int i = 0; i < 16; i++)
                s[i] += __shfl_xor_sync(0xffffffffu, s[i], off);
        if (lane < 4) {
            float* pp = part_s + wid * 64;
#pragma unroll
            for (int nt = 0; nt < 8; nt++)
                *(float2*)(pp + nt * 8 + lane * 2) = make_float2(s[nt * 2], s[nt * 2 + 1]);
        }
        __syncthreads();

        // --- cross-quarter reduce -> g_agg
        if (tid < 128) {
            int nl = tid >> 6, col = tid & 63;
            const float* pp = part_s + nl * 4 * 64 + col;
            g_agg[(size_t)(node0 + nl) * NH + col] =
                pp[0] + pp[64] + pp[128] + pp[192];
        }
    }
}

// ---------------------------------------------------------------------------
// Kernel 3: node MLP over all nodes. One (b,t) per block (392 blocks x 256).
__global__ void __launch_bounds__(256)
k_node_mlp(const float* __restrict__ inputs,
           const float* __restrict__ out1_b,
           const float* __restrict__ out2_b,
           const float* __restrict__ out3_w, const float* __restrict__ out3_b,
           float* __restrict__ out) {
    __shared__ float m1_s[64 * 65];
    __shared__ float m2_s[64 * 65];

    const int bt   = blockIdx.x;
    const int t    = bt % TO;
    const int b    = bt / TO;
    const int tid  = threadIdx.x;
    const int lane = tid & 31;
    const int wid  = tid >> 5;
    const int r0   = wid * 8;

    // ---- layer 1: [x(4), agg(64)] -> 64, relu
    {
        float a[8][2];
#pragma unroll
        for (int r = 0; r < 8; r++) {
            a[r][0] = out1_b[lane];
            a[r][1] = out1_b[lane + 32];
        }
#pragma unroll
        for (int d = 0; d < ND; d++) {
            float w0 = g_w1t[d * NH + lane];
            float w1 = g_w1t[d * NH + lane + 32];
#pragma unroll
            for (int r = 0; r < 8; r++) {
                float xv = inputs[(((size_t)b * NN + (r0 + r)) * NT + t) * ND + d];
                a[r][0] += w0 * xv;
                a[r][1] += w1 * xv;
            }
        }
        const float* ag = g_agg + ((size_t)bt * NN + r0) * NH;
        for (int k = 0; k < NH; k++) {
            float w0 = g_w1t[(ND + k) * NH + lane];
            float w1 = g_w1t[(ND + k) * NH + lane + 32];
#pragma unroll
            for (int r = 0; r < 8; r++) {
                float av = ag[r * NH + k];
                a[r][0] += w0 * av;
                a[r][1] += w1 * av;
            }
        }
#pragma unroll
        for (int r = 0; r < 8; r++) {
            m1_s[(r0 + r) * 65 + lane]      = fmaxf(a[r][0], 0.f);
            m1_s[(r0 + r) * 65 + lane + 32] = fmaxf(a[r][1], 0.f);
        }
    }
    __syncthreads();

    // ---- layer 2: 64 -> 64, relu
    {
        float a[8][2];
#pragma unroll
        for (int r = 0; r < 8; r++) {
            a[r][0] = out2_b[lane];
            a[r][1] = out2_b[lane + 32];
        }
        for (int k = 0; k < NH; k++) {
            float w0 = g_w2nt[k * NH + lane];
            float w1 = g_w2nt[k * NH + lane + 32];
#pragma unroll
            for (int r = 0; r < 8; r++) {
                float mv = m1_s[(r0 + r) * 65 + k];
                a[r][0] += w0 * mv;
                a[r][1] += w1 * mv;
            }
        }
#pragma unroll
        for (int r = 0; r < 8; r++) {
            m2_s[(r0 + r) * 65 + lane]      = fmaxf(a[r][0], 0.f);
            m2_s[(r0 + r) * 65 + lane + 32] = fmaxf(a[r][1], 0.f);
        }
    }
    __syncthreads();

    // ---- layer 3: 64 -> 4, + residual x, write output
    if (tid < 64) {
        const int n = tid;
        float a3[4];
#pragma unroll
        for (int d = 0; d < ND; d++) a3[d] = out3_b[d];
        for (int k = 0; k < NH; k++) {
            float mv = m2_s[n * 65 + k];
#pragma unroll
            for (int d = 0; d < ND; d++) a3[d] += out3_w[d * NH + k] * mv;
        }
        const float* x = inputs + (((size_t)b * NN + n) * NT + t) * ND;
        float* op = out + (((size_t)b * NN + n) * TO + t) * ND;
#pragma unroll
        for (int d = 0; d < ND; d++) op[d] = x[d] + a3[d];
    }
}

// ---------------------------------------------------------------------------
extern "C" void kernel_launch(void* const* d_in, const int* in_sizes, int n_in,
                              void* d_out, int out_size) {
    const float* inputs   = (const float*)d_in[0];
    const float* rel_type = (const float*)d_in[1];
    const float* fc1_w    = (const float*)d_in[4];
    const float* fc1_b    = (const float*)d_in[5];
    const float* fc2_w    = (const float*)d_in[6];
    const float* fc2_b    = (const float*)d_in[7];
    const float* out1_w   = (const float*)d_in[8];
    const float* out1_b   = (const float*)d_in[9];
    const float* out2_w   = (const float*)d_in[10];
    const float* out2_b   = (const float*)d_in[11];
    const float* out3_w   = (const float*)d_in[12];
    const float* out3_b   = (const float*)d_in[13];
    float* out = (float*)d_out;

    const int n_embed = NNODES * NH;
    k_node_embed<<<(n_embed + 255) / 256, 256>>>(inputs, fc1_w, fc1_b, out1_w, out2_w);

    k_edge_mma<<<GRID, 256>>>(rel_type, fc2_w, fc2_b);

    k_node_mlp<<<NBT, 256>>>(inputs, out1_b, out2_b, out3_w, out3_b, out);
}

// round 13
// speedup vs baseline: 1.1908x; 1.1908x over previous
#include <cuda_runtime.h>
#include <cuda_fp16.h>
#include <cstdint>

#define NB 8
#define NN 64
#define NT 50
#define TO 49
#define ND 4
#define NH 64
#define EPN 63
#define NNODES (NB * TO * NN)     // 25088
#define NTILES (NNODES / 2)       // 12544
#define GRID 296
#define EREL (NN * EPN)           // 4032
#define NBT (NB * TO)             // 392

typedef unsigned int u32;

__device__ __half g_uh[NNODES * NH];      // fp16 u' = W1r@x + b1
__device__ __half g_vh[NNODES * NH];      // fp16 v  = W1s@x
__device__ float g_agg[NNODES * NH];      // edge-aggregated messages
__device__ float g_w1t[(ND + NH) * NH];   // out1_w^T: [k][o]
__device__ float g_w2nt[NH * NH];         // out2_w^T: [k][o]

// ---- edge-kernel smem layout (bytes) ---------------------------------------
#define OFF_A    0                // 128 rows x 128B fp16 = 16384 (SW128)
#define OFF_RT   16384            // 128 f
#define SMEM_SZ  16896

#define SWZ(o) ((o) ^ (((o) >> 3) & 0x70))

static __device__ __forceinline__ u32 smem_u32(const void* p) {
    u32 a;
    asm("{ .reg .u64 t; cvta.to.shared.u64 t, %1; cvt.u32.u64 %0, t; }" : "=r"(a) : "l"(p));
    return a;
}
static __device__ __forceinline__ void ldm4(u32* r, u32 addr) {
    asm volatile("ldmatrix.sync.aligned.m8n8.x4.shared.b16 {%0,%1,%2,%3}, [%4];"
        : "=r"(r[0]), "=r"(r[1]), "=r"(r[2]), "=r"(r[3]) : "r"(addr));
}
static __device__ __forceinline__ void mma_f16(float* c, const u32* a, u32 b0, u32 b1) {
    asm volatile("mma.sync.aligned.m16n8k16.row.col.f32.f16.f16.f32 "
        "{%0,%1,%2,%3}, {%4,%5,%6,%7}, {%8,%9}, {%0,%1,%2,%3};"
        : "+f"(c[0]), "+f"(c[1]), "+f"(c[2]), "+f"(c[3])
        : "r"(a[0]), "r"(a[1]), "r"(a[2]), "r"(a[3]), "r"(b0), "r"(b1));
}
static __device__ __forceinline__ u32 hfx2(float x, float y) {
    __half2 p = __floats2half2_rn(x, y);
    return *(u32*)&p;
}
static __device__ __forceinline__ u32 hadd2_relu(u32 a, u32 b) {
    __half2 s = __hadd2(*(__half2*)&a, *(__half2*)&b);
    __half2 z = __float2half2_rn(0.f);
    __half2 r = __hmax2(s, z);
    return *(u32*)&r;
}

// ---------------------------------------------------------------------------
// Kernel 1: per-node fc1 factorization (fp32 math, fp16 store) + transposes.
__global__ void k_node_embed(const float* __restrict__ inputs,
                             const float* __restrict__ fc1_w,
                             const float* __restrict__ fc1_b,
                             const float* __restrict__ out1_w,
                             const float* __restrict__ out2_w) {
    int gid = blockIdx.x * blockDim.x + threadIdx.x;
    if (gid < (ND + NH) * NH) {
        int k = gid >> 6, o = gid & 63;
        g_w1t[k * NH + o] = out1_w[o * (ND + NH) + k];
    }
    if (gid < NH * NH) {
        int k = gid >> 6, o = gid & 63;
        g_w2nt[k * NH + o] = out2_w[o * NH + k];
    }
    if (gid >= NNODES * NH) return;
    int h    = gid & 63;
    int node = gid >> 6;
    int n    = node & 63;
    int bt   = node >> 6;
    int t    = bt % TO;
    int b    = bt / TO;

    const float* x = inputs + (((size_t)b * NN + n) * NT + t) * ND;
    const float* w = fc1_w + NH * 2 * ND + h * 2 * ND;
    float u = fc1_b[NH + h];
    float v = 0.f;
#pragma unroll
    for (int d = 0; d < ND; d++) {
        u += w[d] * x[d];
        v += w[ND + d] * x[d];
    }
    g_uh[gid] = __float2half_rn(u);
    g_vh[gid] = __float2half_rn(v);
}

// ---------------------------------------------------------------------------
// Kernel 2: persistent mma.sync edge-GEMM (fp16 A, fp16 W2 single pass).
// R11 structure: 2 nodes/iteration; warp = (node mh = wid>>2, col-quarter
// nq = wid&3); 4 mt row-tiles per warp; cheap 4-value shfl reduction.
__global__ void __launch_bounds__(256, 2)
k_edge_mma(const float* __restrict__ rel_type,
           const float* __restrict__ fc2_w, const float* __restrict__ fc2_b) {
    __shared__ __align__(1024) char smem[SMEM_SZ];
    const u32 smb = smem_u32(smem);
    const int tid  = threadIdx.x;
    const int lane = tid & 31;
    const int wid  = tid >> 5;
    const int mh   = wid >> 2;       // node within tile (0/1)
    const int nq   = wid & 3;        // col quarter

    float* rt_s = (float*)(smem + OFF_RT);    // [2][64]

    // --- W2 B-fragments (fp16, single pass) into registers, once.
    u32 bfr[4][2][2];
    float bj0[2], bj1[2];
#pragma unroll
    for (int kt = 0; kt < 4; kt++)
#pragma unroll
        for (int nt = 0; nt < 2; nt++) {
            int k0  = kt * 16 + (lane & 3) * 2;
            int col = nq * 16 + nt * 8 + (lane >> 2);
            const float* wc = fc2_w + NH * NH + col * NH;
            bfr[kt][nt][0] = hfx2(wc[k0],     wc[k0 + 1]);
            bfr[kt][nt][1] = hfx2(wc[k0 + 8], wc[k0 + 9]);
        }
#pragma unroll
    for (int nt = 0; nt < 2; nt++) {
        int col = nq * 16 + nt * 8 + (lane & 3) * 2;
        bj0[nt] = fc2_b[NH + col];
        bj1[nt] = fc2_b[NH + col + 1];
    }

    for (int tile = blockIdx.x; tile < NTILES; tile += GRID) {
        const int node0 = tile * 2;
        const int bt = node0 >> 6;
        const int b  = bt / TO;
        const int n0 = node0 & 63;

        __syncthreads();   // prev iteration's rt/A consumers retired

        if (tid < 128) {
            int nl = tid >> 6, s = tid & 63;
            rt_s[tid] = (s < EPN)
                ? rel_type[((size_t)b * EREL + (n0 + nl) * EPN + s) * 2 + 1] : 0.f;
        }

        // --- stage A, coalesced: warp covers 2 full 128B rows per iteration.
        {
            const int seg = lane & 15;            // 8B chunk
            const int rl  = lane >> 4;
#pragma unroll
            for (int it = 0; it < 8; it++) {
                const int r  = wid * 16 + it * 2 + rl;
                const int nl = r >> 6;
                const int s  = r & 63;
                const int nr = n0 + nl;
                const int send = (s >= EPN) ? nr : (s + (s >= nr ? 1 : 0));
                const uint2* uu = (const uint2*)(g_uh + ((size_t)(node0 + nl)) * NH) + seg;
                const uint2* vv = (const uint2*)(g_vh + ((size_t)(bt * NN) + send) * NH) + seg;
                uint2 ua = *uu;
                uint2 va = *vv;
                uint2 hv;
                hv.x = hadd2_relu(ua.x, va.x);
                hv.y = hadd2_relu(ua.y, va.y);
                u32 off = r * 128 + seg * 8;
                *(uint2*)(smem + OFF_A + SWZ(off)) = hv;
            }
        }
        __syncthreads();

        // --- MMA: 4 mt row-tiles x 2 nt x 4 kt, single fp16 pass.
        float acc[4][2][4];
#pragma unroll
        for (int mt = 0; mt < 4; mt++)
#pragma unroll
            for (int nt = 0; nt < 2; nt++)
#pragma unroll
                for (int q = 0; q < 4; q++) acc[mt][nt][q] = 0.f;

#pragma unroll
        for (int kt = 0; kt < 4; kt++) {
            u32 ah[4][4];
            const int rrow  = (lane & 15);
            const int kbyte = kt * 32 + (lane >> 4) * 16;
#pragma unroll
            for (int mt = 0; mt < 4; mt++) {
                u32 o = (mh * 64 + mt * 16 + rrow) * 128 + kbyte;
                ldm4(ah[mt], smb + OFF_A + SWZ(o));
            }
#pragma unroll
            for (int nt = 0; nt < 2; nt++)
#pragma unroll
                for (int mt = 0; mt < 4; mt++)
                    mma_f16(acc[mt][nt], ah[mt], bfr[kt][nt][0], bfr[kt][nt][1]);
        }

        // --- epilogue + in-warp edge reduction -> g_agg
        float red4[4];
#pragma unroll
        for (int nt = 0; nt < 2; nt++) {
            float s0 = 0.f, s1 = 0.f;
#pragma unroll
            for (int mt = 0; mt < 4; mt++) {
                float r0 = rt_s[mh * 64 + mt * 16 + (lane >> 2)];
                float r8 = rt_s[mh * 64 + mt * 16 + (lane >> 2) + 8];
                s0 += fmaxf(acc[mt][nt][0] + bj0[nt], 0.f) * r0
                    + fmaxf(acc[mt][nt][2] + bj0[nt], 0.f) * r8;
                s1 += fmaxf(acc[mt][nt][1] + bj1[nt], 0.f) * r0
                    + fmaxf(acc[mt][nt][3] + bj1[nt], 0.f) * r8;
            }
            red4[nt * 2]     = s0;
            red4[nt * 2 + 1] = s1;
        }
#pragma unroll
        for (int off = 4; off < 32; off <<= 1)
#pragma unroll
            for (int i = 0; i < 4; i++)
                red4[i] += __shfl_xor_sync(0xffffffffu, red4[i], off);
        if (lane < 4) {
            float* ga = g_agg + (size_t)(node0 + mh) * NH + nq * 16 + lane * 2;
            *(float2*)(ga)     = make_float2(red4[0], red4[1]);
            *(float2*)(ga + 8) = make_float2(red4[2], red4[3]);
        }
    }
}

// ---------------------------------------------------------------------------
// Kernel 3: node MLP over all nodes. One (b,t) per block (392 blocks x 256).
__global__ void __launch_bounds__(256)
k_node_mlp(const float* __restrict__ inputs,
           const float* __restrict__ out1_b,
           const float* __restrict__ out2_b,
           const float* __restrict__ out3_w, const float* __restrict__ out3_b,
           float* __restrict__ out) {
    __shared__ float m1_s[64 * 65];
    __shared__ float m2_s[64 * 65];

    const int bt   = blockIdx.x;
    const int t    = bt % TO;
    const int b    = bt / TO;
    const int tid  = threadIdx.x;
    const int lane = tid & 31;
    const int wid  = tid >> 5;
    const int r0   = wid * 8;

    // ---- layer 1: [x(4), agg(64)] -> 64, relu
    {
        float a[8][2];
#pragma unroll
        for (int r = 0; r < 8; r++) {
            a[r][0] = out1_b[lane];
            a[r][1] = out1_b[lane + 32];
        }
#pragma unroll
        for (int d = 0; d < ND; d++) {
            float w0 = g_w1t[d * NH + lane];
            float w1 = g_w1t[d * NH + lane + 32];
#pragma unroll
            for (int r = 0; r < 8; r++) {
                float xv = inputs[(((size_t)b * NN + (r0 + r)) * NT + t) * ND + d];
                a[r][0] += w0 * xv;
                a[r][1] += w1 * xv;
            }
        }
        const float* ag = g_agg + ((size_t)bt * NN + r0) * NH;
        for (int k = 0; k < NH; k++) {
            float w0 = g_w1t[(ND + k) * NH + lane];
            float w1 = g_w1t[(ND + k) * NH + lane + 32];
#pragma unroll
            for (int r = 0; r < 8; r++) {
                float av = ag[r * NH + k];
                a[r][0] += w0 * av;
                a[r][1] += w1 * av;
            }
        }
#pragma unroll
        for (int r = 0; r < 8; r++) {
            m1_s[(r0 + r) * 65 + lane]      = fmaxf(a[r][0], 0.f);
            m1_s[(r0 + r) * 65 + lane + 32] = fmaxf(a[r][1], 0.f);
        }
    }
    __syncthreads();

    // ---- layer 2: 64 -> 64, relu
    {
        float a[8][2];
#pragma unroll
        for (int r = 0; r < 8; r++) {
            a[r][0] = out2_b[lane];
            a[r][1] = out2_b[lane + 32];
        }
        for (int k = 0; k < NH; k++) {
            float w0 = g_w2nt[k * NH + lane];
            float w1 = g_w2nt[k * NH + lane + 32];
#pragma unroll
            for (int r = 0; r < 8; r++) {
                float mv = m1_s[(r0 + r) * 65 + k];
                a[r][0] += w0 * mv;
                a[r][1] += w1 * mv;
            }
        }
#pragma unroll
        for (int r = 0; r < 8; r++) {
            m2_s[(r0 + r) * 65 + lane]      = fmaxf(a[r][0], 0.f);
            m2_s[(r0 + r) * 65 + lane + 32] = fmaxf(a[r][1], 0.f);
        }
    }
    __syncthreads();

    // ---- layer 3: 64 -> 4, + residual x, write output
    if (tid < 64) {
        const int n = tid;
        float a3[4];
#pragma unroll
        for (int d = 0; d < ND; d++) a3[d] = out3_b[d];
        for (int k = 0; k < NH; k++) {
            float mv = m2_s[n * 65 + k];
#pragma unroll
            for (int d = 0; d < ND; d++) a3[d] += out3_w[d * NH + k] * mv;
        }
        const float* x = inputs + (((size_t)b * NN + n) * NT + t) * ND;
        float* op = out + (((size_t)b * NN + n) * TO + t) * ND;
#pragma unroll
        for (int d = 0; d < ND; d++) op[d] = x[d] + a3[d];
    }
}

// ---------------------------------------------------------------------------
extern "C" void kernel_launch(void* const* d_in, const int* in_sizes, int n_in,
                              void* d_out, int out_size) {
    const float* inputs   = (const float*)d_in[0];
    const float* rel_type = (const float*)d_in[1];
    const float* fc1_w    = (const float*)d_in[4];
    const float* fc1_b    = (const float*)d_in[5];
    const float* fc2_w    = (const float*)d_in[6];
    const float* fc2_b    = (const float*)d_in[7];
    const float* out1_w   = (const float*)d_in[8];
    const float* out1_b   = (const float*)d_in[9];
    const float* out2_w   = (const float*)d_in[10];
    const float* out2_b   = (const float*)d_in[11];
    const float* out3_w   = (const float*)d_in[12];
    const float* out3_b   = (const float*)d_in[13];
    float* out = (float*)d_out;

    const int n_embed = NNODES * NH;
    k_node_embed<<<(n_embed + 255) / 256, 256>>>(inputs, fc1_w, fc1_b, out1_w, out2_w);

    k_edge_mma<<<GRID, 256>>>(rel_type, fc2_w, fc2_b);

    k_node_mlp<<<NBT, 256>>>(inputs, out1_b, out2_b, out3_w, out3_b, out);
}

// round 14
// speedup vs baseline: 1.3012x; 1.0928x over previous
#include <cuda_runtime.h>
#include <cuda_fp16.h>
#include <cstdint>

#define NB 8
#define NN 64
#define NT 50
#define TO 49
#define ND 4
#define NH 64
#define EPN 63
#define NNODES (NB * TO * NN)     // 25088
#define NT4 (NNODES / 4)          // 6272 (tile = 4 adjacent recv nodes)
#define GRID 296
#define EREL (NN * EPN)           // 4032
#define NBT (NB * TO)             // 392

typedef unsigned int u32;

__device__ __half g_uh[NNODES * NH];      // fp16 u' = W1r@x + b1
__device__ __half g_vh[NNODES * NH];      // fp16 v  = W1s@x
__device__ float g_agg[NNODES * NH];      // edge-aggregated messages
__device__ float g_w1t[(ND + NH) * NH];   // out1_w^T: [k][o]
__device__ float g_w2nt[NH * NH];         // out2_w^T: [k][o]

// ---- edge-kernel smem layout (bytes) ---------------------------------------
#define OFF_A    0                // 256 rows x 128B fp16 = 32768 (SW128)
#define OFF_RT   32768            // 256 f = 1024
#define OFF_BIAS 33792            // 64 f = 256
#define SMEM_SZ  34048

#define SWZ(o) ((o) ^ (((o) >> 3) & 0x70))

static __device__ __forceinline__ u32 smem_u32(const void* p) {
    u32 a;
    asm("{ .reg .u64 t; cvta.to.shared.u64 t, %1; cvt.u32.u64 %0, t; }" : "=r"(a) : "l"(p));
    return a;
}
static __device__ __forceinline__ void ldm4(u32* r, u32 addr) {
    asm volatile("ldmatrix.sync.aligned.m8n8.x4.shared.b16 {%0,%1,%2,%3}, [%4];"
        : "=r"(r[0]), "=r"(r[1]), "=r"(r[2]), "=r"(r[3]) : "r"(addr));
}
static __device__ __forceinline__ void mma_f16(float* c, const u32* a, u32 b0, u32 b1) {
    asm volatile("mma.sync.aligned.m16n8k16.row.col.f32.f16.f16.f32 "
        "{%0,%1,%2,%3}, {%4,%5,%6,%7}, {%8,%9}, {%0,%1,%2,%3};"
        : "+f"(c[0]), "+f"(c[1]), "+f"(c[2]), "+f"(c[3])
        : "r"(a[0]), "r"(a[1]), "r"(a[2]), "r"(a[3]), "r"(b0), "r"(b1));
}
static __device__ __forceinline__ u32 hfx2(float x, float y) {
    __half2 p = __floats2half2_rn(x, y);
    return *(u32*)&p;
}
static __device__ __forceinline__ u32 hadd2_relu(u32 a, u32 b) {
    __half2 s = __hadd2(*(__half2*)&a, *(__half2*)&b);
    __half2 z = __float2half2_rn(0.f);
    __half2 r = __hmax2(s, z);
    return *(u32*)&r;
}

// ---------------------------------------------------------------------------
// Kernel 1: per-node fc1 factorization (vectorized) + node-MLP transposes.
__global__ void k_node_embed(const float* __restrict__ inputs,
                             const float* __restrict__ fc1_w,
                             const float* __restrict__ fc1_b,
                             const float* __restrict__ out1_w,
                             const float* __restrict__ out2_w) {
    int gid = blockIdx.x * blockDim.x + threadIdx.x;
    if (gid < (ND + NH) * NH) {
        int k = gid >> 6, o = gid & 63;
        g_w1t[k * NH + o] = out1_w[o * (ND + NH) + k];
    }
    if (gid < NH * NH) {
        int k = gid >> 6, o = gid & 63;
        g_w2nt[k * NH + o] = out2_w[o * NH + k];
    }
    if (gid >= NNODES * NH) return;
    int h    = gid & 63;
    int node = gid >> 6;
    int n    = node & 63;
    int bt   = node >> 6;
    int t    = bt % TO;
    int b    = bt / TO;

    const float4 xv = *(const float4*)(inputs + (((size_t)b * NN + n) * NT + t) * ND);
    const float4* w4 = (const float4*)(fc1_w + NH * 2 * ND + h * 2 * ND);
    float4 wa = w4[0], wb = w4[1];
    float u = fc1_b[NH + h] + wa.x * xv.x + wa.y * xv.y + wa.z * xv.z + wa.w * xv.w;
    float v = wb.x * xv.x + wb.y * xv.y + wb.z * xv.z + wb.w * xv.w;
    g_uh[gid] = __float2half_rn(u);
    g_vh[gid] = __float2half_rn(v);
}

// ---------------------------------------------------------------------------
// Kernel 2: persistent mma.sync edge-GEMM (fp16 single pass), 4 nodes/tile.
// 8 warps: nl = wid>>1 (node 0..3), ch = wid&1 (32-col half). Each warp owns
// all 64 rows of its node x 32 cols -> full in-warp edge reduction, and A
// fragments are read only 2x (LDSM halved vs col-quarter layout).
__global__ void __launch_bounds__(256, 2)
k_edge_mma(const float* __restrict__ rel_type,
           const float* __restrict__ fc2_w, const float* __restrict__ fc2_b) {
    __shared__ __align__(1024) char smem[SMEM_SZ];
    const u32 smb = smem_u32(smem);
    const int tid  = threadIdx.x;
    const int lane = tid & 31;
    const int wid  = tid >> 5;
    const int nl   = wid >> 1;       // node within tile (0..3)
    const int ch   = wid & 1;        // col half (32 cols)

    float* rt_s   = (float*)(smem + OFF_RT);    // [4][64]
    float* bias_s = (float*)(smem + OFF_BIAS);  // [64]

    if (tid < 64) bias_s[tid] = fc2_b[NH + tid];

    // --- W2 B-fragments (fp16, single pass): 4 kt x 4 nt x 2 = 32 regs.
    u32 bfr[4][4][2];
#pragma unroll
    for (int kt = 0; kt < 4; kt++)
#pragma unroll
        for (int nt = 0; nt < 4; nt++) {
            int k0  = kt * 16 + (lane & 3) * 2;
            int col = ch * 32 + nt * 8 + (lane >> 2);
            const float* wc = fc2_w + NH * NH + col * NH;
            bfr[kt][nt][0] = hfx2(wc[k0],     wc[k0 + 1]);
            bfr[kt][nt][1] = hfx2(wc[k0 + 8], wc[k0 + 9]);
        }
    __syncthreads();   // bias_s visible

    for (int tile = blockIdx.x; tile < NT4; tile += GRID) {
        const int node0 = tile * 4;
        const int bt = node0 >> 6;
        const int b  = bt / TO;
        const int n0 = node0 & 63;

        __syncthreads();   // prev iteration's rt/A consumers retired

        {
            int nn = tid >> 6, s = tid & 63;
            rt_s[tid] = (s < EPN)
                ? rel_type[((size_t)b * EREL + (n0 + nn) * EPN + s) * 2 + 1] : 0.f;
        }

        // --- stage A, coalesced: warp covers rows wid*32..+32, 2 rows/iter.
        {
            const int seg = lane & 15;            // 8B chunk
            const int rl  = lane >> 4;
#pragma unroll
            for (int it = 0; it < 16; it++) {
                const int r  = wid * 32 + it * 2 + rl;
                const int n4 = r >> 6;
                const int s  = r & 63;
                const int nr = n0 + n4;
                const int send = (s >= EPN) ? nr : (s + (s >= nr ? 1 : 0));
                const uint2* uu = (const uint2*)(g_uh + ((size_t)(node0 + n4)) * NH) + seg;
                const uint2* vv = (const uint2*)(g_vh + ((size_t)(bt * NN) + send) * NH) + seg;
                uint2 ua = *uu;
                uint2 va = *vv;
                uint2 hv;
                hv.x = hadd2_relu(ua.x, va.x);
                hv.y = hadd2_relu(ua.y, va.y);
                u32 off = r * 128 + seg * 8;
                *(uint2*)(smem + OFF_A + SWZ(off)) = hv;
            }
        }
        __syncthreads();

        // --- MMA: 4 mt row-tiles (node nl's 64 rows) x 4 nt x 4 kt.
        float acc[4][4][4];
#pragma unroll
        for (int mt = 0; mt < 4; mt++)
#pragma unroll
            for (int nt = 0; nt < 4; nt++)
#pragma unroll
                for (int q = 0; q < 4; q++) acc[mt][nt][q] = 0.f;

#pragma unroll
        for (int kt = 0; kt < 4; kt++) {
            u32 ah[4][4];
            const int rrow  = (lane & 15);
            const int kbyte = kt * 32 + (lane >> 4) * 16;
#pragma unroll
            for (int mt = 0; mt < 4; mt++) {
                u32 o = (nl * 64 + mt * 16 + rrow) * 128 + kbyte;
                ldm4(ah[mt], smb + OFF_A + SWZ(o));
            }
#pragma unroll
            for (int nt = 0; nt < 4; nt++)
#pragma unroll
                for (int mt = 0; mt < 4; mt++)
                    mma_f16(acc[mt][nt], ah[mt], bfr[kt][nt][0], bfr[kt][nt][1]);
        }

        // --- epilogue: relu(+bias)*rt, full in-warp reduction over 64 rows.
        float s[8];
#pragma unroll
        for (int nt = 0; nt < 4; nt++) {
            float b0 = bias_s[ch * 32 + nt * 8 + (lane & 3) * 2];
            float b1 = bias_s[ch * 32 + nt * 8 + (lane & 3) * 2 + 1];
            float s0 = 0.f, s1 = 0.f;
#pragma unroll
            for (int mt = 0; mt < 4; mt++) {
                float r0 = rt_s[nl * 64 + mt * 16 + (lane >> 2)];
                float r8 = rt_s[nl * 64 + mt * 16 + (lane >> 2) + 8];
                s0 += fmaxf(acc[mt][nt][0] + b0, 0.f) * r0
                    + fmaxf(acc[mt][nt][2] + b0, 0.f) * r8;
                s1 += fmaxf(acc[mt][nt][1] + b1, 0.f) * r0
                    + fmaxf(acc[mt][nt][3] + b1, 0.f) * r8;
            }
            s[nt * 2]     = s0;
            s[nt * 2 + 1] = s1;
        }
#pragma unroll
        for (int off = 4; off < 32; off <<= 1)
#pragma unroll
            for (int i = 0; i < 8; i++)
                s[i] += __shfl_xor_sync(0xffffffffu, s[i], off);
        if (lane < 4) {
            float* ga = g_agg + (size_t)(node0 + nl) * NH + ch * 32 + lane * 2;
#pragma unroll
            for (int nt = 0; nt < 4; nt++)
                *(float2*)(ga + nt * 8) = make_float2(s[nt * 2], s[nt * 2 + 1]);
        }
    }
}

// ---------------------------------------------------------------------------
// Kernel 3: node MLP over all nodes. One (b,t) per block (392 blocks x 256).
__global__ void __launch_bounds__(256)
k_node_mlp(const float* __restrict__ inputs,
           const float* __restrict__ out1_b,
           const float* __restrict__ out2_b,
           const float* __restrict__ out3_w, const float* __restrict__ out3_b,
           float* __restrict__ out) {
    __shared__ float m1_s[64 * 65];
    __shared__ float m2_s[64 * 65];

    const int bt   = blockIdx.x;
    const int t    = bt % TO;
    const int b    = bt / TO;
    const int tid  = threadIdx.x;
    const int lane = tid & 31;
    const int wid  = tid >> 5;
    const int r0   = wid * 8;

    // ---- layer 1: [x(4), agg(64)] -> 64, relu
    {
        float a[8][2];
#pragma unroll
        for (int r = 0; r < 8; r++) {
            a[r][0] = out1_b[lane];
            a[r][1] = out1_b[lane + 32];
        }
#pragma unroll
        for (int d = 0; d < ND; d++) {
            float w0 = g_w1t[d * NH + lane];
            float w1 = g_w1t[d * NH + lane + 32];
#pragma unroll
            for (int r = 0; r < 8; r++) {
                float xv = inputs[(((size_t)b * NN + (r0 + r)) * NT + t) * ND + d];
                a[r][0] += w0 * xv;
                a[r][1] += w1 * xv;
            }
        }
        const float* ag = g_agg + ((size_t)bt * NN + r0) * NH;
        for (int k = 0; k < NH; k++) {
            float w0 = g_w1t[(ND + k) * NH + lane];
            float w1 = g_w1t[(ND + k) * NH + lane + 32];
#pragma unroll
            for (int r = 0; r < 8; r++) {
                float av = ag[r * NH + k];
                a[r][0] += w0 * av;
                a[r][1] += w1 * av;
            }
        }
#pragma unroll
        for (int r = 0; r < 8; r++) {
            m1_s[(r0 + r) * 65 + lane]      = fmaxf(a[r][0], 0.f);
            m1_s[(r0 + r) * 65 + lane + 32] = fmaxf(a[r][1], 0.f);
        }
    }
    __syncthreads();

    // ---- layer 2: 64 -> 64, relu
    {
        float a[8][2];
#pragma unroll
        for (int r = 0; r < 8; r++) {
            a[r][0] = out2_b[lane];
            a[r][1] = out2_b[lane + 32];
        }
        for (int k = 0; k < NH; k++) {
            float w0 = g_w2nt[k * NH + lane];
            float w1 = g_w2nt[k * NH + lane + 32];
#pragma unroll
            for (int r = 0; r < 8; r++) {
                float mv = m1_s[(r0 + r) * 65 + k];
                a[r][0] += w0 * mv;
                a[r][1] += w1 * mv;
            }
        }
#pragma unroll
        for (int r = 0; r < 8; r++) {
            m2_s[(r0 + r) * 65 + lane]      = fmaxf(a[r][0], 0.f);
            m2_s[(r0 + r) * 65 + lane + 32] = fmaxf(a[r][1], 0.f);
        }
    }
    __syncthreads();

    // ---- layer 3: 64 -> 4, + residual x, write output
    if (tid < 64) {
        const int n = tid;
        float a3[4];
#pragma unroll
        for (int d = 0; d < ND; d++) a3[d] = out3_b[d];
        for (int k = 0; k < NH; k++) {
            float mv = m2_s[n * 65 + k];
#pragma unroll
            for (int d = 0; d < ND; d++) a3[d] += out3_w[d * NH + k] * mv;
        }
        const float* x = inputs + (((size_t)b * NN + n) * NT + t) * ND;
        float* op = out + (((size_t)b * NN + n) * TO + t) * ND;
#pragma unroll
        for (int d = 0; d < ND; d++) op[d] = x[d] + a3[d];
    }
}

// ---------------------------------------------------------------------------
extern "C" void kernel_launch(void* const* d_in, const int* in_sizes, int n_in,
                              void* d_out, int out_size) {
    const float* inputs   = (const float*)d_in[0];
    const float* rel_type = (const float*)d_in[1];
    const float* fc1_w    = (const float*)d_in[4];
    const float* fc1_b    = (const float*)d_in[5];
    const float* fc2_w    = (const float*)d_in[6];
    const float* fc2_b    = (const float*)d_in[7];
    const float* out1_w   = (const float*)d_in[8];
    const float* out1_b   = (const float*)d_in[9];
    const float* out2_w   = (const float*)d_in[10];
    const float* out2_b   = (const float*)d_in[11];
    const float* out3_w   = (const float*)d_in[12];
    const float* out3_b   = (const float*)d_in[13];
    float* out = (float*)d_out;

    const int n_embed = NNODES * NH;
    k_node_embed<<<(n_embed + 255) / 256, 256>>>(inputs, fc1_w, fc1_b, out1_w, out2_w);

    k_edge_mma<<<GRID, 256>>>(rel_type, fc2_w, fc2_b);

    k_node_mlp<<<NBT, 256>>>(inputs, out1_b, out2_b, out3_w, out3_b, out);
}

// round 15
// speedup vs baseline: 1.3161x; 1.0115x over previous
#include <cuda_runtime.h>
#include <cuda_fp16.h>
#include <cstdint>

#define NB 8
#define NN 64
#define NT 50
#define TO 49
#define ND 4
#define NH 64
#define EPN 63
#define NNODES (NB * TO * NN)     // 25088
#define NT2 (NNODES / 2)          // 12544 (tile = 2 adjacent recv nodes)
#define GRID 592                  // 148 SMs x 4 CTAs (128 thr each)
#define EREL (NN * EPN)           // 4032
#define NBT (NB * TO)             // 392

typedef unsigned int u32;

__device__ __half g_uh[NNODES * NH];      // fp16 u' = W1r@x + b1
__device__ __half g_vh[NNODES * NH];      // fp16 v  = W1s@x
__device__ float g_agg[NNODES * NH];      // edge-aggregated messages
__device__ float g_w1t[(ND + NH) * NH];   // out1_w^T: [k][o]
__device__ float g_w2nt[NH * NH];         // out2_w^T: [k][o]

// ---- edge-kernel smem layout (bytes) ---------------------------------------
#define OFF_A    0                // 128 rows x 128B fp16 = 16384 (SW128)
#define OFF_RT   16384            // 128 f = 512
#define OFF_BIAS 16896            // 64 f = 256
#define SMEM_SZ  17152

#define SWZ(o) ((o) ^ (((o) >> 3) & 0x70))

static __device__ __forceinline__ u32 smem_u32(const void* p) {
    u32 a;
    asm("{ .reg .u64 t; cvta.to.shared.u64 t, %1; cvt.u32.u64 %0, t; }" : "=r"(a) : "l"(p));
    return a;
}
static __device__ __forceinline__ void ldm4(u32* r, u32 addr) {
    asm volatile("ldmatrix.sync.aligned.m8n8.x4.shared.b16 {%0,%1,%2,%3}, [%4];"
        : "=r"(r[0]), "=r"(r[1]), "=r"(r[2]), "=r"(r[3]) : "r"(addr));
}
static __device__ __forceinline__ void mma_f16(float* c, const u32* a, u32 b0, u32 b1) {
    asm volatile("mma.sync.aligned.m16n8k16.row.col.f32.f16.f16.f32 "
        "{%0,%1,%2,%3}, {%4,%5,%6,%7}, {%8,%9}, {%0,%1,%2,%3};"
        : "+f"(c[0]), "+f"(c[1]), "+f"(c[2]), "+f"(c[3])
        : "r"(a[0]), "r"(a[1]), "r"(a[2]), "r"(a[3]), "r"(b0), "r"(b1));
}
static __device__ __forceinline__ u32 hfx2(float x, float y) {
    __half2 p = __floats2half2_rn(x, y);
    return *(u32*)&p;
}
static __device__ __forceinline__ u32 hadd2_relu(u32 a, u32 b) {
    __half2 s = __hadd2(*(__half2*)&a, *(__half2*)&b);
    __half2 z = __float2half2_rn(0.f);
    __half2 r = __hmax2(s, z);
    return *(u32*)&r;
}

// ---------------------------------------------------------------------------
// Kernel 1: per-node fc1 factorization (vectorized) + node-MLP transposes.
__global__ void k_node_embed(const float* __restrict__ inputs,
                             const float* __restrict__ fc1_w,
                             const float* __restrict__ fc1_b,
                             const float* __restrict__ out1_w,
                             const float* __restrict__ out2_w) {
    int gid = blockIdx.x * blockDim.x + threadIdx.x;
    if (gid < (ND + NH) * NH) {
        int k = gid >> 6, o = gid & 63;
        g_w1t[k * NH + o] = out1_w[o * (ND + NH) + k];
    }
    if (gid < NH * NH) {
        int k = gid >> 6, o = gid & 63;
        g_w2nt[k * NH + o] = out2_w[o * NH + k];
    }
    if (gid >= NNODES * NH) return;
    int h    = gid & 63;
    int node = gid >> 6;
    int n    = node & 63;
    int bt   = node >> 6;
    int t    = bt % TO;
    int b    = bt / TO;

    const float4 xv = *(const float4*)(inputs + (((size_t)b * NN + n) * NT + t) * ND);
    const float4* w4 = (const float4*)(fc1_w + NH * 2 * ND + h * 2 * ND);
    float4 wa = w4[0], wb = w4[1];
    float u = fc1_b[NH + h] + wa.x * xv.x + wa.y * xv.y + wa.z * xv.z + wa.w * xv.w;
    float v = wb.x * xv.x + wb.y * xv.y + wb.z * xv.z + wb.w * xv.w;
    g_uh[gid] = __float2half_rn(u);
    g_vh[gid] = __float2half_rn(v);
}

// ---------------------------------------------------------------------------
// Kernel 2: persistent mma.sync edge-GEMM (fp16 single pass).
// 128-thread CTAs, 4 per SM (4 independent streams to hide staging latency).
// Tile = 2 nodes; 4 warps: nl = wid>>1 (node), ch = wid&1 (32-col half);
// each warp: 4 mt row-tiles x 4 nt x 4 kt, full in-warp edge reduction.
__global__ void __launch_bounds__(128, 4)
k_edge_mma(const float* __restrict__ rel_type,
           const float* __restrict__ fc2_w, const float* __restrict__ fc2_b) {
    __shared__ __align__(1024) char smem[SMEM_SZ];
    const u32 smb = smem_u32(smem);
    const int tid  = threadIdx.x;
    const int lane = tid & 31;
    const int wid  = tid >> 5;
    const int nl   = wid >> 1;       // node within tile (0/1)
    const int ch   = wid & 1;        // col half (32 cols)

    float* rt_s   = (float*)(smem + OFF_RT);    // [2][64]
    float* bias_s = (float*)(smem + OFF_BIAS);  // [64]

    if (tid < 64) bias_s[tid] = fc2_b[NH + tid];

    // --- W2 B-fragments (fp16, single pass): 4 kt x 4 nt x 2 = 32 regs.
    u32 bfr[4][4][2];
#pragma unroll
    for (int kt = 0; kt < 4; kt++)
#pragma unroll
        for (int nt = 0; nt < 4; nt++) {
            int k0  = kt * 16 + (lane & 3) * 2;
            int col = ch * 32 + nt * 8 + (lane >> 2);
            const float* wc = fc2_w + NH * NH + col * NH;
            bfr[kt][nt][0] = hfx2(wc[k0],     wc[k0 + 1]);
            bfr[kt][nt][1] = hfx2(wc[k0 + 8], wc[k0 + 9]);
        }
    __syncthreads();   // bias_s visible

    for (int tile = blockIdx.x; tile < NT2; tile += GRID) {
        const int node0 = tile * 2;
        const int bt = node0 >> 6;
        const int b  = bt / TO;
        const int n0 = node0 & 63;

        __syncthreads();   // prev iteration's rt/A consumers retired

        if (tid < 128) {
            int nn = tid >> 6, s = tid & 63;
            rt_s[tid] = (s < EPN)
                ? rel_type[((size_t)b * EREL + (n0 + nn) * EPN + s) * 2 + 1] : 0.f;
        }

        // --- stage A, coalesced: warp covers rows wid*32..+32, 2 rows/iter.
        {
            const int seg = lane & 15;            // 8B chunk
            const int rl  = lane >> 4;
#pragma unroll
            for (int it = 0; it < 16; it++) {
                const int r  = wid * 32 + it * 2 + rl;
                const int n2 = r >> 6;
                const int s  = r & 63;
                const int nr = n0 + n2;
                const int send = (s >= EPN) ? nr : (s + (s >= nr ? 1 : 0));
                const uint2* uu = (const uint2*)(g_uh + ((size_t)(node0 + n2)) * NH) + seg;
                const uint2* vv = (const uint2*)(g_vh + ((size_t)(bt * NN) + send) * NH) + seg;
                uint2 ua = *uu;
                uint2 va = *vv;
                uint2 hv;
                hv.x = hadd2_relu(ua.x, va.x);
                hv.y = hadd2_relu(ua.y, va.y);
                u32 off = r * 128 + seg * 8;
                *(uint2*)(smem + OFF_A + SWZ(off)) = hv;
            }
        }
        __syncthreads();

        // --- MMA: 4 mt row-tiles (node nl's 64 rows) x 4 nt x 4 kt.
        float acc[4][4][4];
#pragma unroll
        for (int mt = 0; mt < 4; mt++)
#pragma unroll
            for (int nt = 0; nt < 4; nt++)
#pragma unroll
                for (int q = 0; q < 4; q++) acc[mt][nt][q] = 0.f;

#pragma unroll
        for (int kt = 0; kt < 4; kt++) {
            u32 ah[4][4];
            const int rrow  = (lane & 15);
            const int kbyte = kt * 32 + (lane >> 4) * 16;
#pragma unroll
            for (int mt = 0; mt < 4; mt++) {
                u32 o = (nl * 64 + mt * 16 + rrow) * 128 + kbyte;
                ldm4(ah[mt], smb + OFF_A + SWZ(o));
            }
#pragma unroll
            for (int nt = 0; nt < 4; nt++)
#pragma unroll
                for (int mt = 0; mt < 4; mt++)
                    mma_f16(acc[mt][nt], ah[mt], bfr[kt][nt][0], bfr[kt][nt][1]);
        }

        // --- epilogue: relu(+bias)*rt, full in-warp reduction over 64 rows.
        float s[8];
#pragma unroll
        for (int nt = 0; nt < 4; nt++) {
            float b0 = bias_s[ch * 32 + nt * 8 + (lane & 3) * 2];
            float b1 = bias_s[ch * 32 + nt * 8 + (lane & 3) * 2 + 1];
            float s0 = 0.f, s1 = 0.f;
#pragma unroll
            for (int mt = 0; mt < 4; mt++) {
                float r0 = rt_s[nl * 64 + mt * 16 + (lane >> 2)];
                float r8 = rt_s[nl * 64 + mt * 16 + (lane >> 2) + 8];
                s0 += fmaxf(acc[mt][nt][0] + b0, 0.f) * r0
                    + fmaxf(acc[mt][nt][2] + b0, 0.f) * r8;
                s1 += fmaxf(acc[mt][nt][1] + b1, 0.f) * r0
                    + fmaxf(acc[mt][nt][3] + b1, 0.f) * r8;
            }
            s[nt * 2]     = s0;
            s[nt * 2 + 1] = s1;
        }
#pragma unroll
        for (int off = 4; off < 32; off <<= 1)
#pragma unroll
            for (int i = 0; i < 8; i++)
                s[i] += __shfl_xor_sync(0xffffffffu, s[i], off);
        if (lane < 4) {
            float* ga = g_agg + (size_t)(node0 + nl) * NH + ch * 32 + lane * 2;
#pragma unroll
            for (int nt = 0; nt < 4; nt++)
                *(float2*)(ga + nt * 8) = make_float2(s[nt * 2], s[nt * 2 + 1]);
        }
    }
}

// ---------------------------------------------------------------------------
// Kernel 3: node MLP over all nodes. One (b,t) per block (392 blocks x 256).
__global__ void __launch_bounds__(256)
k_node_mlp(const float* __restrict__ inputs,
           const float* __restrict__ out1_b,
           const float* __restrict__ out2_b,
           const float* __restrict__ out3_w, const float* __restrict__ out3_b,
           float* __restrict__ out) {
    __shared__ float m1_s[64 * 65];
    __shared__ float m2_s[64 * 65];

    const int bt   = blockIdx.x;
    const int t    = bt % TO;
    const int b    = bt / TO;
    const int tid  = threadIdx.x;
    const int lane = tid & 31;
    const int wid  = tid >> 5;
    const int r0   = wid * 8;

    // ---- layer 1: [x(4), agg(64)] -> 64, relu
    {
        float a[8][2];
#pragma unroll
        for (int r = 0; r < 8; r++) {
            a[r][0] = out1_b[lane];
            a[r][1] = out1_b[lane + 32];
        }
#pragma unroll
        for (int d = 0; d < ND; d++) {
            float w0 = g_w1t[d * NH + lane];
            float w1 = g_w1t[d * NH + lane + 32];
#pragma unroll
            for (int r = 0; r < 8; r++) {
                float xv = inputs[(((size_t)b * NN + (r0 + r)) * NT + t) * ND + d];
                a[r][0] += w0 * xv;
                a[r][1] += w1 * xv;
            }
        }
        const float* ag = g_agg + ((size_t)bt * NN + r0) * NH;
        for (int k = 0; k < NH; k++) {
            float w0 = g_w1t[(ND + k) * NH + lane];
            float w1 = g_w1t[(ND + k) * NH + lane + 32];
#pragma unroll
            for (int r = 0; r < 8; r++) {
                float av = ag[r * NH + k];
                a[r][0] += w0 * av;
                a[r][1] += w1 * av;
            }
        }
#pragma unroll
        for (int r = 0; r < 8; r++) {
            m1_s[(r0 + r) * 65 + lane]      = fmaxf(a[r][0], 0.f);
            m1_s[(r0 + r) * 65 + lane + 32] = fmaxf(a[r][1], 0.f);
        }
    }
    __syncthreads();

    // ---- layer 2: 64 -> 64, relu
    {
        float a[8][2];
#pragma unroll
        for (int r = 0; r < 8; r++) {
            a[r][0] = out2_b[lane];
            a[r][1] = out2_b[lane + 32];
        }
        for (int k = 0; k < NH; k++) {
            float w0 = g_w2nt[k * NH + lane];
            float w1 = g_w2nt[k * NH + lane + 32];
#pragma unroll
            for (int r = 0; r < 8; r++) {
                float mv = m1_s[(r0 + r) * 65 + k];
                a[r][0] += w0 * mv;
                a[r][1] += w1 * mv;
            }
        }
#pragma unroll
        for (int r = 0; r < 8; r++) {
            m2_s[(r0 + r) * 65 + lane]      = fmaxf(a[r][0], 0.f);
            m2_s[(r0 + r) * 65 + lane + 32] = fmaxf(a[r][1], 0.f);
        }
    }
    __syncthreads();

    // ---- layer 3: 64 -> 4, + residual x, write output
    if (tid < 64) {
        const int n = tid;
        float a3[4];
#pragma unroll
        for (int d = 0; d < ND; d++) a3[d] = out3_b[d];
        for (int k = 0; k < NH; k++) {
            float mv = m2_s[n * 65 + k];
#pragma unroll
            for (int d = 0; d < ND; d++) a3[d] += out3_w[d * NH + k] * mv;
        }
        const float* x = inputs + (((size_t)b * NN + n) * NT + t) * ND;
        float* op = out + (((size_t)b * NN + n) * TO + t) * ND;
#pragma unroll
        for (int d = 0; d < ND; d++) op[d] = x[d] + a3[d];
    }
}

// ---------------------------------------------------------------------------
extern "C" void kernel_launch(void* const* d_in, const int* in_sizes, int n_in,
                              void* d_out, int out_size) {
    const float* inputs   = (const float*)d_in[0];
    const float* rel_type = (const float*)d_in[1];
    const float* fc1_w    = (const float*)d_in[4];
    const float* fc1_b    = (const float*)d_in[5];
    const float* fc2_w    = (const float*)d_in[6];
    const float* fc2_b    = (const float*)d_in[7];
    const float* out1_w   = (const float*)d_in[8];
    const float* out1_b   = (const float*)d_in[9];
    const float* out2_w   = (const float*)d_in[10];
    const float* out2_b   = (const float*)d_in[11];
    const float* out3_w   = (const float*)d_in[12];
    const float* out3_b   = (const float*)d_in[13];
    float* out = (float*)d_out;

    const int n_embed = NNODES * NH;
    k_node_embed<<<(n_embed + 255) / 256, 256>>>(inputs, fc1_w, fc1_b, out1_w, out2_w);

    k_edge_mma<<<GRID, 128>>>(rel_type, fc2_w, fc2_b);

    k_node_mlp<<<NBT, 256>>>(inputs, out1_b, out2_b, out3_w, out3_b, out);
}

// round 16
// speedup vs baseline: 1.3873x; 1.0541x over previous
#include <cuda_runtime.h>
#include <cuda_fp16.h>
#include <cstdint>

#define NB 8
#define NN 64
#define NT 50
#define TO 49
#define ND 4
#define NH 64
#define EPN 63
#define NNODES (NB * TO * NN)     // 25088
#define NT2 (NNODES / 2)          // 12544 (tile = 2 adjacent recv nodes)
#define GRID 592                  // 148 SMs x 4 CTAs (128 thr each)
#define EREL (NN * EPN)           // 4032
#define NBT (NB * TO)             // 392

typedef unsigned int u32;

__device__ __half g_uh[NNODES * NH];      // fp16 u' = W1r@x + b1
__device__ __half g_vh[NNODES * NH];      // fp16 v  = W1s@x
__device__ float g_agg[NNODES * NH];      // edge-aggregated messages
__device__ float g_w1t[(ND + NH) * NH];   // out1_w^T: [k][o]
__device__ float g_w2nt[NH * NH];         // out2_w^T: [k][o]

// ---- edge-kernel smem layout (bytes) ---------------------------------------
#define OFF_A    0                // 128 rows x 128B fp16 = 16384 (SW128)
#define OFF_RT   16384            // 128 f = 512
#define OFF_BIAS 16896            // 64 f = 256
#define SMEM_SZ  17152

#define SWZ(o) ((o) ^ (((o) >> 3) & 0x70))

static __device__ __forceinline__ u32 smem_u32(const void* p) {
    u32 a;
    asm("{ .reg .u64 t; cvta.to.shared.u64 t, %1; cvt.u32.u64 %0, t; }" : "=r"(a) : "l"(p));
    return a;
}
static __device__ __forceinline__ void ldm4(u32* r, u32 addr) {
    asm volatile("ldmatrix.sync.aligned.m8n8.x4.shared.b16 {%0,%1,%2,%3}, [%4];"
        : "=r"(r[0]), "=r"(r[1]), "=r"(r[2]), "=r"(r[3]) : "r"(addr));
}
static __device__ __forceinline__ void mma_f16(float* c, const u32* a, u32 b0, u32 b1) {
    asm volatile("mma.sync.aligned.m16n8k16.row.col.f32.f16.f16.f32 "
        "{%0,%1,%2,%3}, {%4,%5,%6,%7}, {%8,%9}, {%0,%1,%2,%3};"
        : "+f"(c[0]), "+f"(c[1]), "+f"(c[2]), "+f"(c[3])
        : "r"(a[0]), "r"(a[1]), "r"(a[2]), "r"(a[3]), "r"(b0), "r"(b1));
}
static __device__ __forceinline__ u32 hfx2(float x, float y) {
    __half2 p = __floats2half2_rn(x, y);
    return *(u32*)&p;
}
static __device__ __forceinline__ u32 hadd2_relu(u32 a, u32 b) {
    __half2 s = __hadd2(*(__half2*)&a, *(__half2*)&b);
    __half2 z = __float2half2_rn(0.f);
    __half2 r = __hmax2(s, z);
    return *(u32*)&r;
}

// ---------------------------------------------------------------------------
// Kernel 1: per-node fc1 factorization (vectorized) + node-MLP transposes.
__global__ void k_node_embed(const float* __restrict__ inputs,
                             const float* __restrict__ fc1_w,
                             const float* __restrict__ fc1_b,
                             const float* __restrict__ out1_w,
                             const float* __restrict__ out2_w) {
    int gid = blockIdx.x * blockDim.x + threadIdx.x;
    if (gid < (ND + NH) * NH) {
        int k = gid >> 6, o = gid & 63;
        g_w1t[k * NH + o] = out1_w[o * (ND + NH) + k];
    }
    if (gid < NH * NH) {
        int k = gid >> 6, o = gid & 63;
        g_w2nt[k * NH + o] = out2_w[o * NH + k];
    }
    if (gid >= NNODES * NH) return;
    int h    = gid & 63;
    int node = gid >> 6;
    int n    = node & 63;
    int bt   = node >> 6;
    int t    = bt % TO;
    int b    = bt / TO;

    const float4 xv = *(const float4*)(inputs + (((size_t)b * NN + n) * NT + t) * ND);
    const float4* w4 = (const float4*)(fc1_w + NH * 2 * ND + h * 2 * ND);
    float4 wa = w4[0], wb = w4[1];
    float u = fc1_b[NH + h] + wa.x * xv.x + wa.y * xv.y + wa.z * xv.z + wa.w * xv.w;
    float v = wb.x * xv.x + wb.y * xv.y + wb.z * xv.z + wb.w * xv.w;
    g_uh[gid] = __float2half_rn(u);
    g_vh[gid] = __float2half_rn(v);
}

// ---------------------------------------------------------------------------
// Kernel 2: persistent mma.sync edge-GEMM (fp16 single pass).
// 128-thread CTAs, 4/SM. CONTIGUOUS tile chunks per CTA: consecutive tiles
// share the same (b,t)'s u/v working set -> staging LDGs become L1 hits
// after the first tile of a bt. uint4 staging (16B/lane, 8 iters).
__global__ void __launch_bounds__(128, 4)
k_edge_mma(const float* __restrict__ rel_type,
           const float* __restrict__ fc2_w, const float* __restrict__ fc2_b) {
    __shared__ __align__(1024) char smem[SMEM_SZ];
    const u32 smb = smem_u32(smem);
    const int tid  = threadIdx.x;
    const int lane = tid & 31;
    const int wid  = tid >> 5;
    const int nl   = wid >> 1;       // node within tile (0/1)
    const int ch   = wid & 1;        // col half (32 cols)

    float* rt_s   = (float*)(smem + OFF_RT);    // [2][64]
    float* bias_s = (float*)(smem + OFF_BIAS);  // [64]

    if (tid < 64) bias_s[tid] = fc2_b[NH + tid];

    // --- W2 B-fragments (fp16, single pass): 4 kt x 4 nt x 2 = 32 regs.
    u32 bfr[4][4][2];
#pragma unroll
    for (int kt = 0; kt < 4; kt++)
#pragma unroll
        for (int nt = 0; nt < 4; nt++) {
            int k0  = kt * 16 + (lane & 3) * 2;
            int col = ch * 32 + nt * 8 + (lane >> 2);
            const float* wc = fc2_w + NH * NH + col * NH;
            bfr[kt][nt][0] = hfx2(wc[k0],     wc[k0 + 1]);
            bfr[kt][nt][1] = hfx2(wc[k0 + 8], wc[k0 + 9]);
        }
    __syncthreads();   // bias_s visible

    // Balanced contiguous chunk: base 21 tiles, first 112 CTAs get 22.
    const int bid  = blockIdx.x;
    const int base = NT2 / GRID;                 // 21
    const int rem  = NT2 - base * GRID;          // 112
    const int t0   = bid * base + (bid < rem ? bid : rem);
    const int cnt  = base + (bid < rem ? 1 : 0);

    for (int tile = t0; tile < t0 + cnt; tile++) {
        const int node0 = tile * 2;
        const int bt = node0 >> 6;
        const int b  = bt / TO;
        const int n0 = node0 & 63;

        __syncthreads();   // prev iteration's rt/A consumers retired

        {
            int nn = tid >> 6, s = tid & 63;
            rt_s[tid] = (s < EPN)
                ? rel_type[((size_t)b * EREL + (n0 + nn) * EPN + s) * 2 + 1] : 0.f;
        }

        // --- stage A, uint4 (16B/lane): warp covers 4 rows/iter, 8 iters.
        {
            const int seg = lane & 7;             // 16B chunk (8 per row)
            const int rl  = lane >> 3;            // row within quad
#pragma unroll
            for (int it = 0; it < 8; it++) {
                const int r  = wid * 32 + it * 4 + rl;
                const int n2 = r >> 6;
                const int s  = r & 63;
                const int nr = n0 + n2;
                const int send = (s >= EPN) ? nr : (s + (s >= nr ? 1 : 0));
                const uint4* uu = (const uint4*)(g_uh + ((size_t)(node0 + n2)) * NH) + seg;
                const uint4* vv = (const uint4*)(g_vh + ((size_t)(bt * NN) + send) * NH) + seg;
                uint4 ua = *uu;
                uint4 va = *vv;
                uint4 hv;
                hv.x = hadd2_relu(ua.x, va.x);
                hv.y = hadd2_relu(ua.y, va.y);
                hv.z = hadd2_relu(ua.z, va.z);
                hv.w = hadd2_relu(ua.w, va.w);
                u32 off = r * 128 + seg * 16;
                *(uint4*)(smem + OFF_A + SWZ(off)) = hv;
            }
        }
        __syncthreads();

        // --- MMA: 4 mt row-tiles (node nl's 64 rows) x 4 nt x 4 kt.
        float acc[4][4][4];
#pragma unroll
        for (int mt = 0; mt < 4; mt++)
#pragma unroll
            for (int nt = 0; nt < 4; nt++)
#pragma unroll
                for (int q = 0; q < 4; q++) acc[mt][nt][q] = 0.f;

#pragma unroll
        for (int kt = 0; kt < 4; kt++) {
            u32 ah[4][4];
            const int rrow  = (lane & 15);
            const int kbyte = kt * 32 + (lane >> 4) * 16;
#pragma unroll
            for (int mt = 0; mt < 4; mt++) {
                u32 o = (nl * 64 + mt * 16 + rrow) * 128 + kbyte;
                ldm4(ah[mt], smb + OFF_A + SWZ(o));
            }
#pragma unroll
            for (int nt = 0; nt < 4; nt++)
#pragma unroll
                for (int mt = 0; mt < 4; mt++)
                    mma_f16(acc[mt][nt], ah[mt], bfr[kt][nt][0], bfr[kt][nt][1]);
        }

        // --- epilogue: relu(+bias)*rt, full in-warp reduction over 64 rows.
        float s[8];
#pragma unroll
        for (int nt = 0; nt < 4; nt++) {
            float b0 = bias_s[ch * 32 + nt * 8 + (lane & 3) * 2];
            float b1 = bias_s[ch * 32 + nt * 8 + (lane & 3) * 2 + 1];
            float s0 = 0.f, s1 = 0.f;
#pragma unroll
            for (int mt = 0; mt < 4; mt++) {
                float r0 = rt_s[nl * 64 + mt * 16 + (lane >> 2)];
                float r8 = rt_s[nl * 64 + mt * 16 + (lane >> 2) + 8];
                s0 += fmaxf(acc[mt][nt][0] + b0, 0.f) * r0
                    + fmaxf(acc[mt][nt][2] + b0, 0.f) * r8;
                s1 += fmaxf(acc[mt][nt][1] + b1, 0.f) * r0
                    + fmaxf(acc[mt][nt][3] + b1, 0.f) * r8;
            }
            s[nt * 2]     = s0;
            s[nt * 2 + 1] = s1;
        }
#pragma unroll
        for (int off = 4; off < 32; off <<= 1)
#pragma unroll
            for (int i = 0; i < 8; i++)
                s[i] += __shfl_xor_sync(0xffffffffu, s[i], off);
        if (lane < 4) {
            float* ga = g_agg + (size_t)(node0 + nl) * NH + ch * 32 + lane * 2;
#pragma unroll
            for (int nt = 0; nt < 4; nt++)
                *(float2*)(ga + nt * 8) = make_float2(s[nt * 2], s[nt * 2 + 1]);
        }
    }
}

// ---------------------------------------------------------------------------
// Kernel 3: node MLP over all nodes. One (b,t) per block (392 blocks x 256).
__global__ void __launch_bounds__(256)
k_node_mlp(const float* __restrict__ inputs,
           const float* __restrict__ out1_b,
           const float* __restrict__ out2_b,
           const float* __restrict__ out3_w, const float* __restrict__ out3_b,
           float* __restrict__ out) {
    __shared__ float m1_s[64 * 65];
    __shared__ float m2_s[64 * 65];

    const int bt   = blockIdx.x;
    const int t    = bt % TO;
    const int b    = bt / TO;
    const int tid  = threadIdx.x;
    const int lane = tid & 31;
    const int wid  = tid >> 5;
    const int r0   = wid * 8;

    // ---- layer 1: [x(4), agg(64)] -> 64, relu
    {
        float a[8][2];
#pragma unroll
        for (int r = 0; r < 8; r++) {
            a[r][0] = out1_b[lane];
            a[r][1] = out1_b[lane + 32];
        }
#pragma unroll
        for (int d = 0; d < ND; d++) {
            float w0 = g_w1t[d * NH + lane];
            float w1 = g_w1t[d * NH + lane + 32];
#pragma unroll
            for (int r = 0; r < 8; r++) {
                float xv = inputs[(((size_t)b * NN + (r0 + r)) * NT + t) * ND + d];
                a[r][0] += w0 * xv;
                a[r][1] += w1 * xv;
            }
        }
        const float* ag = g_agg + ((size_t)bt * NN + r0) * NH;
        for (int k = 0; k < NH; k++) {
            float w0 = g_w1t[(ND + k) * NH + lane];
            float w1 = g_w1t[(ND + k) * NH + lane + 32];
#pragma unroll
            for (int r = 0; r < 8; r++) {
                float av = ag[r * NH + k];
                a[r][0] += w0 * av;
                a[r][1] += w1 * av;
            }
        }
#pragma unroll
        for (int r = 0; r < 8; r++) {
            m1_s[(r0 + r) * 65 + lane]      = fmaxf(a[r][0], 0.f);
            m1_s[(r0 + r) * 65 + lane + 32] = fmaxf(a[r][1], 0.f);
        }
    }
    __syncthreads();

    // ---- layer 2: 64 -> 64, relu
    {
        float a[8][2];
#pragma unroll
        for (int r = 0; r < 8; r++) {
            a[r][0] = out2_b[lane];
            a[r][1] = out2_b[lane + 32];
        }
        for (int k = 0; k < NH; k++) {
            float w0 = g_w2nt[k * NH + lane];
            float w1 = g_w2nt[k * NH + lane + 32];
#pragma unroll
            for (int r = 0; r < 8; r++) {
                float mv = m1_s[(r0 + r) * 65 + k];
                a[r][0] += w0 * mv;
                a[r][1] += w1 * mv;
            }
        }
#pragma unroll
        for (int r = 0; r < 8; r++) {
            m2_s[(r0 + r) * 65 + lane]      = fmaxf(a[r][0], 0.f);
            m2_s[(r0 + r) * 65 + lane + 32] = fmaxf(a[r][1], 0.f);
        }
    }
    __syncthreads();

    // ---- layer 3: 64 -> 4, + residual x, write output
    if (tid < 64) {
        const int n = tid;
        float a3[4];
#pragma unroll
        for (int d = 0; d < ND; d++) a3[d] = out3_b[d];
        for (int k = 0; k < NH; k++) {
            float mv = m2_s[n * 65 + k];
#pragma unroll
            for (int d = 0; d < ND; d++) a3[d] += out3_w[d * NH + k] * mv;
        }
        const float* x = inputs + (((size_t)b * NN + n) * NT + t) * ND;
        float* op = out + (((size_t)b * NN + n) * TO + t) * ND;
#pragma unroll
        for (int d = 0; d < ND; d++) op[d] = x[d] + a3[d];
    }
}

// ---------------------------------------------------------------------------
extern "C" void kernel_launch(void* const* d_in, const int* in_sizes, int n_in,
                              void* d_out, int out_size) {
    const float* inputs   = (const float*)d_in[0];
    const float* rel_type = (const float*)d_in[1];
    const float* fc1_w    = (const float*)d_in[4];
    const float* fc1_b    = (const float*)d_in[5];
    const float* fc2_w    = (const float*)d_in[6];
    const float* fc2_b    = (const float*)d_in[7];
    const float* out1_w   = (const float*)d_in[8];
    const float* out1_b   = (const float*)d_in[9];
    const float* out2_w   = (const float*)d_in[10];
    const float* out2_b   = (const float*)d_in[11];
    const float* out3_w   = (const float*)d_in[12];
    const float* out3_b   = (const float*)d_in[13];
    float* out = (float*)d_out;

    const int n_embed = NNODES * NH;
    k_node_embed<<<(n_embed + 255) / 256, 256>>>(inputs, fc1_w, fc1_b, out1_w, out2_w);

    k_edge_mma<<<GRID, 128>>>(rel_type, fc2_w, fc2_b);

    k_node_mlp<<<NBT, 256>>>(inputs, out1_b, out2_b, out3_w, out3_b, out);
}

// round 17
// speedup vs baseline: 1.3957x; 1.0061x over previous
#include <cuda_runtime.h>
#include <cuda_fp16.h>
#include <cstdint>

#define NB 8
#define NN 64
#define NT 50
#define TO 49
#define ND 4
#define NH 64
#define EPN 63
#define NNODES (NB * TO * NN)     // 25088
#define NT2 (NNODES / 2)          // 12544 (tile = 2 adjacent recv nodes)
#define GRID 592                  // 148 SMs x 4 CTAs (128 thr each)
#define EREL (NN * EPN)           // 4032
#define NBT (NB * TO)             // 392

typedef unsigned int u32;

__device__ __half g_uh[NNODES * NH];      // fp16 u' = W1r@x + b1
__device__ __half g_vh[NNODES * NH];      // fp16 v  = W1s@x
__device__ float g_agg[NNODES * NH];      // edge-aggregated messages
__device__ float g_w1t[(ND + NH) * NH];   // out1_w^T: [k][o]
__device__ float g_w2nt[NH * NH];         // out2_w^T: [k][o]

// ---- edge-kernel smem layout (bytes): DOUBLE-BUFFERED A and rt -------------
#define ABUF     16384
#define OFF_A    0                // 2 x (128 rows x 128B) = 32768 (SW128)
#define OFF_RT   32768            // 2 x 128 f = 1024
#define OFF_BIAS 33792            // 64 f = 256
#define SMEM_SZ  34048

#define SWZ(o) ((o) ^ (((o) >> 3) & 0x70))

static __device__ __forceinline__ u32 smem_u32(const void* p) {
    u32 a;
    asm("{ .reg .u64 t; cvta.to.shared.u64 t, %1; cvt.u32.u64 %0, t; }" : "=r"(a) : "l"(p));
    return a;
}
static __device__ __forceinline__ void ldm4(u32* r, u32 addr) {
    asm volatile("ldmatrix.sync.aligned.m8n8.x4.shared.b16 {%0,%1,%2,%3}, [%4];"
        : "=r"(r[0]), "=r"(r[1]), "=r"(r[2]), "=r"(r[3]) : "r"(addr));
}
static __device__ __forceinline__ void mma_f16(float* c, const u32* a, u32 b0, u32 b1) {
    asm volatile("mma.sync.aligned.m16n8k16.row.col.f32.f16.f16.f32 "
        "{%0,%1,%2,%3}, {%4,%5,%6,%7}, {%8,%9}, {%0,%1,%2,%3};"
        : "+f"(c[0]), "+f"(c[1]), "+f"(c[2]), "+f"(c[3])
        : "r"(a[0]), "r"(a[1]), "r"(a[2]), "r"(a[3]), "r"(b0), "r"(b1));
}
static __device__ __forceinline__ u32 hfx2(float x, float y) {
    __half2 p = __floats2half2_rn(x, y);
    return *(u32*)&p;
}
static __device__ __forceinline__ u32 hadd2_relu(u32 a, u32 b) {
    __half2 s = __hadd2(*(__half2*)&a, *(__half2*)&b);
    __half2 z = __float2half2_rn(0.f);
    __half2 r = __hmax2(s, z);
    return *(u32*)&r;
}

// ---------------------------------------------------------------------------
// Kernel 1: per-node fc1 factorization (vectorized) + node-MLP transposes.
__global__ void k_node_embed(const float* __restrict__ inputs,
                             const float* __restrict__ fc1_w,
                             const float* __restrict__ fc1_b,
                             const float* __restrict__ out1_w,
                             const float* __restrict__ out2_w) {
    int gid = blockIdx.x * blockDim.x + threadIdx.x;
    if (gid < (ND + NH) * NH) {
        int k = gid >> 6, o = gid & 63;
        g_w1t[k * NH + o] = out1_w[o * (ND + NH) + k];
    }
    if (gid < NH * NH) {
        int k = gid >> 6, o = gid & 63;
        g_w2nt[k * NH + o] = out2_w[o * NH + k];
    }
    if (gid >= NNODES * NH) return;
    int h    = gid & 63;
    int node = gid >> 6;
    int n    = node & 63;
    int bt   = node >> 6;
    int t    = bt % TO;
    int b    = bt / TO;

    const float4 xv = *(const float4*)(inputs + (((size_t)b * NN + n) * NT + t) * ND);
    const float4* w4 = (const float4*)(fc1_w + NH * 2 * ND + h * 2 * ND);
    float4 wa = w4[0], wb = w4[1];
    float u = fc1_b[NH + h] + wa.x * xv.x + wa.y * xv.y + wa.z * xv.z + wa.w * xv.w;
    float v = wb.x * xv.x + wb.y * xv.y + wb.z * xv.z + wb.w * xv.w;
    g_uh[gid] = __float2half_rn(u);
    g_vh[gid] = __float2half_rn(v);
}

// ---------------------------------------------------------------------------
// Stage one tile's A (h = relu(u+v), fp16) and rt into buffer `buf`.
static __device__ __forceinline__ void stage_tile(
    char* smem, int tile, int tid, int wid, int lane,
    const float* __restrict__ rel_type, int buf) {
    const int node0 = tile * 2;
    const int bt = node0 >> 6;
    const int b  = bt / TO;
    const int n0 = node0 & 63;

    float* rt_s = (float*)(smem + OFF_RT) + buf * 128;
    {
        int nn = tid >> 6, s = tid & 63;
        rt_s[tid] = (s < EPN)
            ? rel_type[((size_t)b * EREL + (n0 + nn) * EPN + s) * 2 + 1] : 0.f;
    }
    const int seg = lane & 7;             // 16B chunk (8 per row)
    const int rl  = lane >> 3;            // row within quad
    char* abuf = smem + OFF_A + buf * ABUF;
#pragma unroll
    for (int it = 0; it < 8; it++) {
        const int r  = wid * 32 + it * 4 + rl;
        const int n2 = r >> 6;
        const int s  = r & 63;
        const int nr = n0 + n2;
        const int send = (s >= EPN) ? nr : (s + (s >= nr ? 1 : 0));
        const uint4* uu = (const uint4*)(g_uh + ((size_t)(node0 + n2)) * NH) + seg;
        const uint4* vv = (const uint4*)(g_vh + ((size_t)(bt * NN) + send) * NH) + seg;
        uint4 ua = *uu;
        uint4 va = *vv;
        uint4 hv;
        hv.x = hadd2_relu(ua.x, va.x);
        hv.y = hadd2_relu(ua.y, va.y);
        hv.z = hadd2_relu(ua.z, va.z);
        hv.w = hadd2_relu(ua.w, va.w);
        u32 off = r * 128 + seg * 16;
        *(uint4*)(abuf + SWZ(off)) = hv;
    }
}

// ---------------------------------------------------------------------------
// Kernel 2: persistent mma.sync edge-GEMM (fp16 single pass), double-buffered.
// 128-thread CTAs, 4/SM; contiguous chunks (L1-resident u/v); per tile:
// one sync, then stage(next) OVERLAPS mma(cur).
__global__ void __launch_bounds__(128, 4)
k_edge_mma(const float* __restrict__ rel_type,
           const float* __restrict__ fc2_w, const float* __restrict__ fc2_b) {
    __shared__ __align__(1024) char smem[SMEM_SZ];
    const u32 smb = smem_u32(smem);
    const int tid  = threadIdx.x;
    const int lane = tid & 31;
    const int wid  = tid >> 5;
    const int nl   = wid >> 1;       // node within tile (0/1)
    const int ch   = wid & 1;        // col half (32 cols)

    float* bias_s = (float*)(smem + OFF_BIAS);

    if (tid < 64) bias_s[tid] = fc2_b[NH + tid];

    // --- W2 B-fragments (fp16, single pass): 4 kt x 4 nt x 2 = 32 regs.
    u32 bfr[4][4][2];
#pragma unroll
    for (int kt = 0; kt < 4; kt++)
#pragma unroll
        for (int nt = 0; nt < 4; nt++) {
            int k0  = kt * 16 + (lane & 3) * 2;
            int col = ch * 32 + nt * 8 + (lane >> 2);
            const float* wc = fc2_w + NH * NH + col * NH;
            bfr[kt][nt][0] = hfx2(wc[k0],     wc[k0 + 1]);
            bfr[kt][nt][1] = hfx2(wc[k0 + 8], wc[k0 + 9]);
        }

    // Balanced contiguous chunk: base 21 tiles, first 112 CTAs get 22.
    const int bid  = blockIdx.x;
    const int base = NT2 / GRID;                 // 21
    const int rem  = NT2 - base * GRID;          // 112
    const int t0   = bid * base + (bid < rem ? bid : rem);
    const int cnt  = base + (bid < rem ? 1 : 0);

    // Prologue: stage first tile into buffer 0.
    stage_tile(smem, t0, tid, wid, lane, rel_type, 0);

    for (int i = 0; i < cnt; i++) {
        const int tile  = t0 + i;
        const int cur   = i & 1;
        const int node0 = tile * 2;
        const int n0    = node0 & 63;

        __syncthreads();   // A[cur]/rt[cur] staged; prev iter fully retired

        // Stage NEXT tile into the other buffer (overlaps with MMA below).
        if (i + 1 < cnt)
            stage_tile(smem, tile + 1, tid, wid, lane, rel_type, cur ^ 1);

        // --- MMA on A[cur]: 4 mt row-tiles (node nl) x 4 nt x 4 kt.
        const u32 abase = smb + OFF_A + cur * ABUF;
        float acc[4][4][4];
#pragma unroll
        for (int mt = 0; mt < 4; mt++)
#pragma unroll
            for (int nt = 0; nt < 4; nt++)
#pragma unroll
                for (int q = 0; q < 4; q++) acc[mt][nt][q] = 0.f;

#pragma unroll
        for (int kt = 0; kt < 4; kt++) {
            u32 ah[4][4];
            const int rrow  = (lane & 15);
            const int kbyte = kt * 32 + (lane >> 4) * 16;
#pragma unroll
            for (int mt = 0; mt < 4; mt++) {
                u32 o = (nl * 64 + mt * 16 + rrow) * 128 + kbyte;
                ldm4(ah[mt], abase + SWZ(o));
            }
#pragma unroll
            for (int nt = 0; nt < 4; nt++)
#pragma unroll
                for (int mt = 0; mt < 4; mt++)
                    mma_f16(acc[mt][nt], ah[mt], bfr[kt][nt][0], bfr[kt][nt][1]);
        }

        // --- epilogue: relu(+bias)*rt, full in-warp reduction over 64 rows.
        const float* rt_s = (float*)(smem + OFF_RT) + cur * 128;
        float s[8];
#pragma unroll
        for (int nt = 0; nt < 4; nt++) {
            float b0 = bias_s[ch * 32 + nt * 8 + (lane & 3) * 2];
            float b1 = bias_s[ch * 32 + nt * 8 + (lane & 3) * 2 + 1];
            float s0 = 0.f, s1 = 0.f;
#pragma unroll
            for (int mt = 0; mt < 4; mt++) {
                float r0 = rt_s[nl * 64 + mt * 16 + (lane >> 2)];
                float r8 = rt_s[nl * 64 + mt * 16 + (lane >> 2) + 8];
                s0 += fmaxf(acc[mt][nt][0] + b0, 0.f) * r0
                    + fmaxf(acc[mt][nt][2] + b0, 0.f) * r8;
                s1 += fmaxf(acc[mt][nt][1] + b1, 0.f) * r0
                    + fmaxf(acc[mt][nt][3] + b1, 0.f) * r8;
            }
            s[nt * 2]     = s0;
            s[nt * 2 + 1] = s1;
        }
#pragma unroll
        for (int off = 4; off < 32; off <<= 1)
#pragma unroll
            for (int j = 0; j < 8; j++)
                s[j] += __shfl_xor_sync(0xffffffffu, s[j], off);
        if (lane < 4) {
            float* ga = g_agg + (size_t)(node0 + nl) * NH + ch * 32 + lane * 2;
#pragma unroll
            for (int nt = 0; nt < 4; nt++)
                *(float2*)(ga + nt * 8) = make_float2(s[nt * 2], s[nt * 2 + 1]);
        }
    }
}

// ---------------------------------------------------------------------------
// Kernel 3: node MLP over all nodes. One (b,t) per block (392 blocks x 256).
__global__ void __launch_bounds__(256)
k_node_mlp(const float* __restrict__ inputs,
           const float* __restrict__ out1_b,
           const float* __restrict__ out2_b,
           const float* __restrict__ out3_w, const float* __restrict__ out3_b,
           float* __restrict__ out) {
    __shared__ float m1_s[64 * 65];
    __shared__ float m2_s[64 * 65];

    const int bt   = blockIdx.x;
    const int t    = bt % TO;
    const int b    = bt / TO;
    const int tid  = threadIdx.x;
    const int lane = tid & 31;
    const int wid  = tid >> 5;
    const int r0   = wid * 8;

    // ---- layer 1: [x(4), agg(64)] -> 64, relu
    {
        float a[8][2];
#pragma unroll
        for (int r = 0; r < 8; r++) {
            a[r][0] = out1_b[lane];
            a[r][1] = out1_b[lane + 32];
        }
#pragma unroll
        for (int d = 0; d < ND; d++) {
            float w0 = g_w1t[d * NH + lane];
            float w1 = g_w1t[d * NH + lane + 32];
#pragma unroll
            for (int r = 0; r < 8; r++) {
                float xv = inputs[(((size_t)b * NN + (r0 + r)) * NT + t) * ND + d];
                a[r][0] += w0 * xv;
                a[r][1] += w1 * xv;
            }
        }
        const float* ag = g_agg + ((size_t)bt * NN + r0) * NH;
        for (int k = 0; k < NH; k++) {
            float w0 = g_w1t[(ND + k) * NH + lane];
            float w1 = g_w1t[(ND + k) * NH + lane + 32];
#pragma unroll
            for (int r = 0; r < 8; r++) {
                float av = ag[r * NH + k];
                a[r][0] += w0 * av;
                a[r][1] += w1 * av;
            }
        }
#pragma unroll
        for (int r = 0; r < 8; r++) {
            m1_s[(r0 + r) * 65 + lane]      = fmaxf(a[r][0], 0.f);
            m1_s[(r0 + r) * 65 + lane + 32] = fmaxf(a[r][1], 0.f);
        }
    }
    __syncthreads();

    // ---- layer 2: 64 -> 64, relu
    {
        float a[8][2];
#pragma unroll
        for (int r = 0; r < 8; r++) {
            a[r][0] = out2_b[lane];
            a[r][1] = out2_b[lane + 32];
        }
        for (int k = 0; k < NH; k++) {
            float w0 = g_w2nt[k * NH + lane];
            float w1 = g_w2nt[k * NH + lane + 32];
#pragma unroll
            for (int r = 0; r < 8; r++) {
                float mv = m1_s[(r0 + r) * 65 + k];
                a[r][0] += w0 * mv;
                a[r][1] += w1 * mv;
            }
        }
#pragma unroll
        for (int r = 0; r < 8; r++) {
            m2_s[(r0 + r) * 65 + lane]      = fmaxf(a[r][0], 0.f);
            m2_s[(r0 + r) * 65 + lane + 32] = fmaxf(a[r][1], 0.f);
        }
    }
    __syncthreads();

    // ---- layer 3: 64 -> 4, + residual x, write output
    if (tid < 64) {
        const int n = tid;
        float a3[4];
#pragma unroll
        for (int d = 0; d < ND; d++) a3[d] = out3_b[d];
        for (int k = 0; k < NH; k++) {
            float mv = m2_s[n * 65 + k];
#pragma unroll
            for (int d = 0; d < ND; d++) a3[d] += out3_w[d * NH + k] * mv;
        }
        const float* x = inputs + (((size_t)b * NN + n) * NT + t) * ND;
        float* op = out + (((size_t)b * NN + n) * TO + t) * ND;
#pragma unroll
        for (int d = 0; d < ND; d++) op[d] = x[d] + a3[d];
    }
}

// ---------------------------------------------------------------------------
extern "C" void kernel_launch(void* const* d_in, const int* in_sizes, int n_in,
                              void* d_out, int out_size) {
    const float* inputs   = (const float*)d_in[0];
    const float* rel_type = (const float*)d_in[1];
    const float* fc1_w    = (const float*)d_in[4];
    const float* fc1_b    = (const float*)d_in[5];
    const float* fc2_w    = (const float*)d_in[6];
    const float* fc2_b    = (const float*)d_in[7];
    const float* out1_w   = (const float*)d_in[8];
    const float* out1_b   = (const float*)d_in[9];
    const float* out2_w   = (const float*)d_in[10];
    const float* out2_b   = (const float*)d_in[11];
    const float* out3_w   = (const float*)d_in[12];
    const float* out3_b   = (const float*)d_in[13];
    float* out = (float*)d_out;

    const int n_embed = NNODES * NH;
    k_node_embed<<<(n_embed + 255) / 256, 256>>>(inputs, fc1_w, fc1_b, out1_w, out2_w);

    k_edge_mma<<<GRID, 128>>>(rel_type, fc2_w, fc2_b);

    k_node_mlp<<<NBT, 256>>>(inputs, out1_b, out2_b, out3_w, out3_b, out);
}